// round 11
// baseline (speedup 1.0000x reference)
#include <cuda_runtime.h>

#define ROWS 8
#define THREADS 512
#define D 4096

typedef unsigned long long u64;

// Transposed+interleaved inner matrices: g_CT[(s*64+g)*16+jc][o] = float4(C[4jc..4jc+3][o])
// where C = (B[s][g] @ H64) / 64
__device__ float g_CT[2 * 64 * 16 * 64 * 4];
// Transposed final matrices: g_FT[rect*8+jc][o] = float4(fB[rect][4jc..4jc+3][o])
__device__ float g_FT[128 * 8 * 32 * 4];

union F4U2 { float4 f; ulonglong2 u; };

__device__ __forceinline__ void fma2(u64& d, u64 a, u64 b) {
    asm("fma.rn.f32x2 %0,%1,%2,%3;" : "=l"(d) : "l"(a), "l"(b), "l"(d));
}
__device__ __forceinline__ float hsum2(u64 a) {
    float lo, hi;
    asm("mov.b64 {%0,%1},%2;" : "=f"(lo), "=f"(hi) : "l"(a));
    return lo + hi;
}
// bank-conflict-avoiding swizzle: logical (block n, col c) -> physical col
__device__ __forceinline__ int swz(int n, int c) {
    return n * 64 + (c ^ ((n & 7) << 3));
}

// ---------------- prepass 1: CT = interleave(transpose((B @ H64) / 64)) ----------------
__global__ void prep_kernel(const float* __restrict__ innerB) {
    const int t = blockIdx.x * blockDim.x + threadIdx.x;   // (s*64+n)*64+i : row i of block
    const int i = t & 63;
    const int sn = t >> 6;
    const float4* src = reinterpret_cast<const float4*>(innerB + (size_t)t * 64);
    float v[64];
    #pragma unroll
    for (int k = 0; k < 16; k++) {
        float4 f = src[k];
        v[4*k] = f.x; v[4*k+1] = f.y; v[4*k+2] = f.z; v[4*k+3] = f.w;
    }
    #pragma unroll
    for (int h = 1; h < 64; h <<= 1)
        #pragma unroll
        for (int m = 0; m < 64; m += 2*h)
            #pragma unroll
            for (int k = 0; k < h; k++) {
                float a = v[m+k], b = v[m+k+h];
                v[m+k] = a + b; v[m+k+h] = a - b;
            }
    // v[o] = C[i][o] (pre-scale); scatter into CT[(sn)*16 + (i>>2)][o][i&3]
    const float s = 1.0f / 64.0f;
    float* dst = g_CT + (((size_t)sn * 16 + (i >> 2)) * 64) * 4 + (i & 3);
    #pragma unroll
    for (int o = 0; o < 64; o++)
        dst[o * 4] = v[o] * s;
}

// ---------------- prepass 2: FT = interleave(transpose(finalB)) ----------------
__global__ void prep_final(const float* __restrict__ finalB) {
    const int t = blockIdx.x * blockDim.x + threadIdx.x;   // rect*32 + i
    const int i = t & 31;
    const int rect = t >> 5;
    const float* src = finalB + (size_t)t * 32;
    float* dst = g_FT + (((size_t)rect * 8 + (i >> 2)) * 32) * 4 + (i & 3);
    #pragma unroll
    for (int o = 0; o < 32; o++)
        dst[o * 4] = src[o];
}

// ---------------- main fused kernel ----------------
__global__ __launch_bounds__(THREADS, 1)
void bh_fused_kernel(const float* __restrict__ x,
                     float* __restrict__ out)
{
    extern __shared__ float sd[];   // ROWS * D floats, swizzled layout
    const int tid = threadIdx.x;
    const size_t row0 = (size_t)blockIdx.x * ROWS;

    // ---- load ROWS rows (coalesced gmem read, swizzled smem store) ----
    {
        const float4* gx = reinterpret_cast<const float4*>(x + row0 * D);
        float4* s4 = reinterpret_cast<float4*>(sd);
        #pragma unroll
        for (int k = 0; k < (ROWS * D / 4) / THREADS; k++) {
            const int f   = tid + k * THREADS;
            const int r   = f >> 10;
            const int cq  = f & 1023;
            const int n   = cq >> 4;
            const int c   = (cq & 15) * 4;
            s4[r * 1024 + (swz(n, c) >> 2)] = gx[f];
        }
    }
    __syncthreads();

    const int t16 = tid & 15;     // thread within group (16 per group)
    const int ghalf = tid >> 4;   // 0..31

    #pragma unroll 1
    for (int stage = 0; stage < 2; stage++) {
        // ---- block-diag 64x64 matmul, j-paired FFMA2, 2 group passes ----
        #pragma unroll 1
        for (int pass = 0; pass < 2; pass++) {
            const int g = ghalf + (pass << 5);
            const float4* CT = reinterpret_cast<const float4*>(g_CT)
                             + ((size_t)(stage * 64 + g) * 16) * 64;

            u64 acc[ROWS][4];
            #pragma unroll
            for (int r = 0; r < ROWS; r++)
                #pragma unroll
                for (int oo = 0; oo < 4; oo++)
                    acc[r][oo] = 0ull;

            #pragma unroll 1
            for (int jc = 0; jc < 16; jc++) {
                F4U2 c[4];
                #pragma unroll
                for (int oo = 0; oo < 4; oo++)
                    c[oo].f = CT[jc * 64 + t16 + 16 * oo];
                const int pj = swz(g, jc * 4);
                #pragma unroll
                for (int r = 0; r < ROWS; r++) {
                    F4U2 xv;
                    xv.f = *reinterpret_cast<const float4*>(&sd[r * D + pj]);
                    #pragma unroll
                    for (int oo = 0; oo < 4; oo++) {
                        fma2(acc[r][oo], xv.u.x, c[oo].u.x);
                        fma2(acc[r][oo], xv.u.y, c[oo].u.y);
                    }
                }
            }
            __syncwarp();   // group reads of its block done before overwrite
            #pragma unroll
            for (int r = 0; r < ROWS; r++)
                #pragma unroll
                for (int oo = 0; oo < 4; oo++)
                    sd[r * D + swz(g, t16 + 16 * oo)] = hsum2(acc[r][oo]);
        }
        __syncthreads();

        // ---- outer H64 (stride-64 across blocks), register-resident ----
        {
            const int hr = tid >> 6;      // row 0..7
            const int hj = tid & 63;      // within-block column
            float v[64];
            #pragma unroll
            for (int m = 0; m < 64; m++)
                v[m] = sd[hr * D + m * 64 + (hj ^ ((m & 7) << 3))];
            #pragma unroll
            for (int h = 1; h < 64; h <<= 1)
                #pragma unroll
                for (int m0 = 0; m0 < 64; m0 += 2*h)
                    #pragma unroll
                    for (int k = 0; k < h; k++) {
                        float a = v[m0+k], b = v[m0+k+h];
                        v[m0+k] = a + b; v[m0+k+h] = a - b;
                    }
            #pragma unroll
            for (int m = 0; m < 64; m++)
                sd[hr * D + m * 64 + (hj ^ ((m & 7) << 3))] = v[m];
        }
        __syncthreads();
    }

    // ---------------- final block-diag 128 x (32x32) matmul -> GMEM ----------------
    {
        const int t8 = tid & 7;
        #pragma unroll 1
        for (int pass = 0; pass < 2; pass++) {
            const int rect = (tid >> 3) + (pass << 6);
            const int n    = rect >> 1;
            const int cb   = (rect & 1) * 32;
            const float4* FT = reinterpret_cast<const float4*>(g_FT)
                             + ((size_t)rect * 8) * 32;

            u64 acc[ROWS][4];
            #pragma unroll
            for (int r = 0; r < ROWS; r++)
                #pragma unroll
                for (int oo = 0; oo < 4; oo++)
                    acc[r][oo] = 0ull;

            #pragma unroll 1
            for (int jc = 0; jc < 8; jc++) {
                F4U2 c[4];
                #pragma unroll
                for (int oo = 0; oo < 4; oo++)
                    c[oo].f = FT[jc * 32 + t8 + 8 * oo];
                const int pj = swz(n, cb + jc * 4);
                #pragma unroll
                for (int r = 0; r < ROWS; r++) {
                    F4U2 xv;
                    xv.f = *reinterpret_cast<const float4*>(&sd[r * D + pj]);
                    #pragma unroll
                    for (int oo = 0; oo < 4; oo++) {
                        fma2(acc[r][oo], xv.u.x, c[oo].u.x);
                        fma2(acc[r][oo], xv.u.y, c[oo].u.y);
                    }
                }
            }
            #pragma unroll
            for (int r = 0; r < ROWS; r++) {
                float* op = out + (row0 + r) * D + rect * 32 + t8;
                #pragma unroll
                for (int oo = 0; oo < 4; oo++)
                    op[8 * oo] = hsum2(acc[r][oo]);
            }
        }
    }
}

extern "C" void kernel_launch(void* const* d_in, const int* in_sizes, int n_in,
                              void* d_out, int out_size) {
    const float* x  = (const float*)d_in[0];   // [4,4096,4096] f32
    const float* iB = (const float*)d_in[1];   // [2,64,64,64]  f32
    const float* fB = (const float*)d_in[2];   // [128,32,32]   f32
    float* out = (float*)d_out;                // [4,4096,4096] f32

    prep_kernel<<<64, 128>>>(iB);
    prep_final<<<32, 128>>>(fB);

    const int smem = ROWS * D * sizeof(float); // 131072 bytes
    cudaFuncSetAttribute(bh_fused_kernel,
                         cudaFuncAttributeMaxDynamicSharedMemorySize, smem);
    const int nrows = 4 * 4096;
    bh_fused_kernel<<<nrows / ROWS, THREADS, smem>>>(x, out);
}

// round 12
// speedup vs baseline: 1.0247x; 1.0247x over previous
#include <cuda_runtime.h>

#define ROWS 8
#define THREADS 512
#define D 4096

typedef unsigned long long u64;

// H-folded, pre-scaled inner matrices: C[s][n] = (B[s][n] @ H64) / 64
__device__ float g_C[2 * 64 * 64 * 64];

__device__ __forceinline__ u64 pack2(float x) {
    u64 r; asm("mov.b64 %0,{%1,%1};" : "=l"(r) : "f"(x)); return r;
}
__device__ __forceinline__ void fma2(u64& d, u64 a, u64 b) {
    asm("fma.rn.f32x2 %0,%1,%2,%3;" : "=l"(d) : "l"(a), "l"(b), "l"(d));
}
// bank-conflict-avoiding swizzle: logical (block n, col c) -> physical col
__device__ __forceinline__ int swz(int n, int c) {
    return n * 64 + (c ^ ((n & 7) << 3));
}

// ---------------- prepass: C = (B @ H64) / 64 ----------------
__global__ void prep_kernel(const float* __restrict__ innerB) {
    const int t = blockIdx.x * blockDim.x + threadIdx.x;   // row of a 64x64 block
    const float4* src = reinterpret_cast<const float4*>(innerB + (size_t)t * 64);
    float v[64];
    #pragma unroll
    for (int k = 0; k < 16; k++) {
        float4 f = src[k];
        v[4*k] = f.x; v[4*k+1] = f.y; v[4*k+2] = f.z; v[4*k+3] = f.w;
    }
    #pragma unroll
    for (int h = 1; h < 64; h <<= 1)
        #pragma unroll
        for (int m = 0; m < 64; m += 2*h)
            #pragma unroll
            for (int k = 0; k < h; k++) {
                float a = v[m+k], b = v[m+k+h];
                v[m+k] = a + b; v[m+k+h] = a - b;
            }
    float4* dst = reinterpret_cast<float4*>(g_C + (size_t)t * 64);
    const float s = 1.0f / 64.0f;
    #pragma unroll
    for (int k = 0; k < 16; k++)
        dst[k] = make_float4(v[4*k]*s, v[4*k+1]*s, v[4*k+2]*s, v[4*k+3]*s);
}

// ---------------- main fused kernel ----------------
__global__ __launch_bounds__(THREADS, 1)
void bh_fused_kernel(const float* __restrict__ x,
                     const float* __restrict__ finalB,
                     float* __restrict__ out)
{
    extern __shared__ float sd[];   // ROWS * D floats, swizzled layout
    const int tid = threadIdx.x;
    const size_t row0 = (size_t)blockIdx.x * ROWS;

    // ---- load ROWS rows (coalesced gmem read, swizzled smem store) ----
    {
        const float4* gx = reinterpret_cast<const float4*>(x + row0 * D);
        float4* s4 = reinterpret_cast<float4*>(sd);
        #pragma unroll
        for (int k = 0; k < (ROWS * D / 4) / THREADS; k++) {
            const int f   = tid + k * THREADS;
            const int r   = f >> 10;
            const int cq  = f & 1023;
            const int n   = cq >> 4;
            const int c   = (cq & 15) * 4;
            s4[r * 1024 + (swz(n, c) >> 2)] = gx[f];
        }
    }
    __syncthreads();

    const int g  = tid >> 3;         // group 0..63 (8 threads per group)
    const int ob = (tid & 7) * 8;    // output-col base within group
    const int pb = swz(g, ob);       // physical col base for writes (8-aligned)

    #pragma unroll 1
    for (int stage = 0; stage < 2; stage++) {
        // ---- block-diag 64x64 matmul with C, register double-buffered LDG ----
        const float* C = g_C + ((size_t)stage * 64 + g) * 64 * 64;

        u64 acc[ROWS][4];
        #pragma unroll
        for (int r = 0; r < ROWS; r++)
            #pragma unroll
            for (int p = 0; p < 4; p++)
                acc[r][p] = 0ull;

        // prologue: load 2-j block 0
        ulonglong2 cc[2][2];
        cc[0][0] = *reinterpret_cast<const ulonglong2*>(&C[0 * 64 + ob]);
        cc[0][1] = *reinterpret_cast<const ulonglong2*>(&C[0 * 64 + ob + 4]);
        cc[1][0] = *reinterpret_cast<const ulonglong2*>(&C[1 * 64 + ob]);
        cc[1][1] = *reinterpret_cast<const ulonglong2*>(&C[1 * 64 + ob + 4]);

        #pragma unroll 1
        for (int jb = 0; jb < 32; jb++) {
            // issue next block's loads before consuming current block
            ulonglong2 cn[2][2];
            if (jb < 31) {
                const int jn = (jb + 1) * 2;
                cn[0][0] = *reinterpret_cast<const ulonglong2*>(&C[jn * 64 + ob]);
                cn[0][1] = *reinterpret_cast<const ulonglong2*>(&C[jn * 64 + ob + 4]);
                cn[1][0] = *reinterpret_cast<const ulonglong2*>(&C[(jn + 1) * 64 + ob]);
                cn[1][1] = *reinterpret_cast<const ulonglong2*>(&C[(jn + 1) * 64 + ob + 4]);
            }
            const int pj = swz(g, jb * 2);     // jb*2 even -> float2-aligned
            #pragma unroll
            for (int r = 0; r < ROWS; r++) {
                const float2 xp = *reinterpret_cast<const float2*>(&sd[r * D + pj]);
                u64 xs = pack2(xp.x);
                fma2(acc[r][0], xs, cc[0][0].x); fma2(acc[r][1], xs, cc[0][0].y);
                fma2(acc[r][2], xs, cc[0][1].x); fma2(acc[r][3], xs, cc[0][1].y);
                xs = pack2(xp.y);
                fma2(acc[r][0], xs, cc[1][0].x); fma2(acc[r][1], xs, cc[1][0].y);
                fma2(acc[r][2], xs, cc[1][1].x); fma2(acc[r][3], xs, cc[1][1].y);
            }
            if (jb < 31) {
                cc[0][0] = cn[0][0]; cc[0][1] = cn[0][1];
                cc[1][0] = cn[1][0]; cc[1][1] = cn[1][1];
            }
        }
        // block g's region is read/written only by its own group (one warp)
        __syncwarp();
        #pragma unroll
        for (int r = 0; r < ROWS; r++) {
            ulonglong2* sp = reinterpret_cast<ulonglong2*>(&sd[r * D + pb]);
            sp[0] = make_ulonglong2(acc[r][0], acc[r][1]);
            sp[1] = make_ulonglong2(acc[r][2], acc[r][3]);
        }
        __syncthreads();

        // ---- outer H64 (stride-64 across blocks), register-resident ----
        {
            const int hr = tid >> 6;      // row 0..7
            const int hj = tid & 63;      // within-block column
            float v[64];
            #pragma unroll
            for (int m = 0; m < 64; m++)
                v[m] = sd[hr * D + m * 64 + (hj ^ ((m & 7) << 3))];
            #pragma unroll
            for (int h = 1; h < 64; h <<= 1)
                #pragma unroll
                for (int m0 = 0; m0 < 64; m0 += 2*h)
                    #pragma unroll
                    for (int k = 0; k < h; k++) {
                        float a = v[m0+k], b = v[m0+k+h];
                        v[m0+k] = a + b; v[m0+k+h] = a - b;
                    }
            #pragma unroll
            for (int m = 0; m < 64; m++)
                sd[hr * D + m * 64 + (hj ^ ((m & 7) << 3))] = v[m];
        }
        __syncthreads();
    }

    // ---------------- final block-diag 128 x (32x32) matmul -> GMEM ----------------
    {
        const int rect = tid >> 2;        // 0..127 (4 threads per rect)
        const int ob2  = (tid & 3) * 8;
        const int n    = rect >> 1;
        const int cb   = (rect & 1) * 32;
        const float* B = finalB + (size_t)rect * 32 * 32;

        u64 acc[ROWS][4];
        #pragma unroll
        for (int r = 0; r < ROWS; r++)
            #pragma unroll
            for (int p = 0; p < 4; p++)
                acc[r][p] = 0ull;

        ulonglong2 cc[2][2];
        cc[0][0] = *reinterpret_cast<const ulonglong2*>(&B[0 * 32 + ob2]);
        cc[0][1] = *reinterpret_cast<const ulonglong2*>(&B[0 * 32 + ob2 + 4]);
        cc[1][0] = *reinterpret_cast<const ulonglong2*>(&B[1 * 32 + ob2]);
        cc[1][1] = *reinterpret_cast<const ulonglong2*>(&B[1 * 32 + ob2 + 4]);

        #pragma unroll 1
        for (int jb = 0; jb < 16; jb++) {
            ulonglong2 cn[2][2];
            if (jb < 15) {
                const int jn = (jb + 1) * 2;
                cn[0][0] = *reinterpret_cast<const ulonglong2*>(&B[jn * 32 + ob2]);
                cn[0][1] = *reinterpret_cast<const ulonglong2*>(&B[jn * 32 + ob2 + 4]);
                cn[1][0] = *reinterpret_cast<const ulonglong2*>(&B[(jn + 1) * 32 + ob2]);
                cn[1][1] = *reinterpret_cast<const ulonglong2*>(&B[(jn + 1) * 32 + ob2 + 4]);
            }
            const int pj = swz(n, cb + jb * 2);
            #pragma unroll
            for (int r = 0; r < ROWS; r++) {
                const float2 xp = *reinterpret_cast<const float2*>(&sd[r * D + pj]);
                u64 xs = pack2(xp.x);
                fma2(acc[r][0], xs, cc[0][0].x); fma2(acc[r][1], xs, cc[0][0].y);
                fma2(acc[r][2], xs, cc[0][1].x); fma2(acc[r][3], xs, cc[0][1].y);
                xs = pack2(xp.y);
                fma2(acc[r][0], xs, cc[1][0].x); fma2(acc[r][1], xs, cc[1][0].y);
                fma2(acc[r][2], xs, cc[1][1].x); fma2(acc[r][3], xs, cc[1][1].y);
            }
            if (jb < 15) {
                cc[0][0] = cn[0][0]; cc[0][1] = cn[0][1];
                cc[1][0] = cn[1][0]; cc[1][1] = cn[1][1];
            }
        }
        #pragma unroll
        for (int r = 0; r < ROWS; r++) {
            ulonglong2* op = reinterpret_cast<ulonglong2*>(out + (row0 + r) * D + rect * 32 + ob2);
            op[0] = make_ulonglong2(acc[r][0], acc[r][1]);
            op[1] = make_ulonglong2(acc[r][2], acc[r][3]);
        }
    }
}

extern "C" void kernel_launch(void* const* d_in, const int* in_sizes, int n_in,
                              void* d_out, int out_size) {
    const float* x  = (const float*)d_in[0];   // [4,4096,4096] f32
    const float* iB = (const float*)d_in[1];   // [2,64,64,64]  f32
    const float* fB = (const float*)d_in[2];   // [128,32,32]   f32
    float* out = (float*)d_out;                // [4,4096,4096] f32

    prep_kernel<<<64, 128>>>(iB);

    const int smem = ROWS * D * sizeof(float); // 131072 bytes
    cudaFuncSetAttribute(bh_fused_kernel,
                         cudaFuncAttributeMaxDynamicSharedMemorySize, smem);
    const int nrows = 4 * 4096;
    bh_fused_kernel<<<nrows / ROWS, THREADS, smem>>>(x, fB, out);
}

// round 13
// speedup vs baseline: 1.0570x; 1.0316x over previous
#include <cuda_runtime.h>

#define ROWS 8
#define THREADS 512
#define D 4096

typedef unsigned long long u64;

// H-folded, pre-scaled inner matrices: C[s][n] = (B[s][n] @ H64) / 64
__device__ float g_C[2 * 64 * 64 * 64];

__device__ __forceinline__ u64 pack2(float x) {
    u64 r; asm("mov.b64 %0,{%1,%1};" : "=l"(r) : "f"(x)); return r;
}
__device__ __forceinline__ void fma2(u64& d, u64 a, u64 b) {
    asm("fma.rn.f32x2 %0,%1,%2,%3;" : "=l"(d) : "l"(a), "l"(b), "l"(d));
}
// bank-conflict-avoiding swizzle: logical (block n, col c) -> physical col
__device__ __forceinline__ int swz(int n, int c) {
    return n * 64 + (c ^ ((n & 7) << 3));
}

// ---------------- prepass: C = (B @ H64) / 64 ----------------
__global__ void prep_kernel(const float* __restrict__ innerB) {
    const int t = blockIdx.x * blockDim.x + threadIdx.x;   // row of a 64x64 block
    const float4* src = reinterpret_cast<const float4*>(innerB + (size_t)t * 64);
    float v[64];
    #pragma unroll
    for (int k = 0; k < 16; k++) {
        float4 f = src[k];
        v[4*k] = f.x; v[4*k+1] = f.y; v[4*k+2] = f.z; v[4*k+3] = f.w;
    }
    #pragma unroll
    for (int h = 1; h < 64; h <<= 1)
        #pragma unroll
        for (int m = 0; m < 64; m += 2*h)
            #pragma unroll
            for (int k = 0; k < h; k++) {
                float a = v[m+k], b = v[m+k+h];
                v[m+k] = a + b; v[m+k+h] = a - b;
            }
    float4* dst = reinterpret_cast<float4*>(g_C + (size_t)t * 64);
    const float s = 1.0f / 64.0f;
    #pragma unroll
    for (int k = 0; k < 16; k++)
        dst[k] = make_float4(v[4*k]*s, v[4*k+1]*s, v[4*k+2]*s, v[4*k+3]*s);
}

// load a 2-j C slab (j0 even): S[0] = row j0 cols[ob..ob+8), S[1] = row j0+1
#define LOADC(S, BASE, STRIDE, J0, OBX)                                              \
    S[0][0] = *reinterpret_cast<const ulonglong2*>(&(BASE)[(J0) * (STRIDE) + (OBX)]);       \
    S[0][1] = *reinterpret_cast<const ulonglong2*>(&(BASE)[(J0) * (STRIDE) + (OBX) + 4]);   \
    S[1][0] = *reinterpret_cast<const ulonglong2*>(&(BASE)[((J0) + 1) * (STRIDE) + (OBX)]); \
    S[1][1] = *reinterpret_cast<const ulonglong2*>(&(BASE)[((J0) + 1) * (STRIDE) + (OBX) + 4]);

// consume a 2-j slab against x pair at physical col PJ
#define COMP2(S, PJ)                                                                 \
    {                                                                                \
        const int pj_ = (PJ);                                                        \
        _Pragma("unroll")                                                            \
        for (int r = 0; r < ROWS; r++) {                                             \
            const float2 xp = *reinterpret_cast<const float2*>(&sd[r * D + pj_]);    \
            u64 xs = pack2(xp.x);                                                    \
            fma2(acc[r][0], xs, S[0][0].x); fma2(acc[r][1], xs, S[0][0].y);          \
            fma2(acc[r][2], xs, S[0][1].x); fma2(acc[r][3], xs, S[0][1].y);          \
            xs = pack2(xp.y);                                                        \
            fma2(acc[r][0], xs, S[1][0].x); fma2(acc[r][1], xs, S[1][0].y);          \
            fma2(acc[r][2], xs, S[1][1].x); fma2(acc[r][3], xs, S[1][1].y);          \
        }                                                                            \
    }

// ---------------- main fused kernel ----------------
__global__ __launch_bounds__(THREADS, 1)
void bh_fused_kernel(const float* __restrict__ x,
                     const float* __restrict__ finalB,
                     float* __restrict__ out)
{
    extern __shared__ float sd[];   // ROWS * D floats, swizzled layout
    const int tid = threadIdx.x;
    const size_t row0 = (size_t)blockIdx.x * ROWS;

    // ---- load ROWS rows (coalesced gmem read, swizzled smem store) ----
    {
        const float4* gx = reinterpret_cast<const float4*>(x + row0 * D);
        float4* s4 = reinterpret_cast<float4*>(sd);
        #pragma unroll
        for (int k = 0; k < (ROWS * D / 4) / THREADS; k++) {
            const int f   = tid + k * THREADS;
            const int r   = f >> 10;
            const int cq  = f & 1023;
            const int n   = cq >> 4;
            const int c   = (cq & 15) * 4;
            s4[r * 1024 + (swz(n, c) >> 2)] = gx[f];
        }
    }
    __syncthreads();

    const int g  = tid >> 3;         // group 0..63 (8 threads per group)
    const int ob = (tid & 7) * 8;    // output-col base within group
    const int pb = swz(g, ob);       // physical col base for writes (8-aligned)

    #pragma unroll 1
    for (int stage = 0; stage < 2; stage++) {
        // ---- block-diag 64x64 matmul with C, ping-pong double-buffered LDG ----
        const float* C = g_C + ((size_t)stage * 64 + g) * 64 * 64;

        u64 acc[ROWS][4];
        #pragma unroll
        for (int r = 0; r < ROWS; r++)
            #pragma unroll
            for (int p = 0; p < 4; p++)
                acc[r][p] = 0ull;

        ulonglong2 A[2][2], Bv[2][2];
        LOADC(A, C, 64, 0, ob)                          // j = 0,1
        #pragma unroll 1
        for (int sb = 0; sb < 16; sb++) {
            const int j0 = sb * 4;
            LOADC(Bv, C, 64, j0 + 2, ob)                // j+2, j+3
            COMP2(A, swz(g, j0))                        // consume j, j+1
            if (sb < 15) { LOADC(A, C, 64, j0 + 4, ob) }// j+4, j+5
            COMP2(Bv, swz(g, j0 + 2))                   // consume j+2, j+3
        }
        // block g's region is read/written only by its own group (one warp)
        __syncwarp();
        #pragma unroll
        for (int r = 0; r < ROWS; r++) {
            ulonglong2* sp = reinterpret_cast<ulonglong2*>(&sd[r * D + pb]);
            sp[0] = make_ulonglong2(acc[r][0], acc[r][1]);
            sp[1] = make_ulonglong2(acc[r][2], acc[r][3]);
        }
        __syncthreads();

        // ---- outer H64 (stride-64 across blocks), register-resident ----
        {
            const int hr = tid >> 6;      // row 0..7
            const int hj = tid & 63;      // within-block column
            float v[64];
            #pragma unroll
            for (int m = 0; m < 64; m++)
                v[m] = sd[hr * D + m * 64 + (hj ^ ((m & 7) << 3))];
            #pragma unroll
            for (int h = 1; h < 64; h <<= 1)
                #pragma unroll
                for (int m0 = 0; m0 < 64; m0 += 2*h)
                    #pragma unroll
                    for (int k = 0; k < h; k++) {
                        float a = v[m0+k], b = v[m0+k+h];
                        v[m0+k] = a + b; v[m0+k+h] = a - b;
                    }
            #pragma unroll
            for (int m = 0; m < 64; m++)
                sd[hr * D + m * 64 + (hj ^ ((m & 7) << 3))] = v[m];
        }
        __syncthreads();
    }

    // ---------------- final block-diag 128 x (32x32) matmul -> GMEM ----------------
    {
        const int rect = tid >> 2;        // 0..127 (4 threads per rect)
        const int ob2  = (tid & 3) * 8;
        const int n    = rect >> 1;
        const int cb   = (rect & 1) * 32;
        const float* B = finalB + (size_t)rect * 32 * 32;

        u64 acc[ROWS][4];
        #pragma unroll
        for (int r = 0; r < ROWS; r++)
            #pragma unroll
            for (int p = 0; p < 4; p++)
                acc[r][p] = 0ull;

        ulonglong2 A[2][2], Bv[2][2];
        LOADC(A, B, 32, 0, ob2)                         // j = 0,1
        #pragma unroll 1
        for (int sb = 0; sb < 8; sb++) {
            const int j0 = sb * 4;
            LOADC(Bv, B, 32, j0 + 2, ob2)
            COMP2(A, swz(n, cb + j0))
            if (sb < 7) { LOADC(A, B, 32, j0 + 4, ob2) }
            COMP2(Bv, swz(n, cb + j0 + 2))
        }
        #pragma unroll
        for (int r = 0; r < ROWS; r++) {
            ulonglong2* op = reinterpret_cast<ulonglong2*>(out + (row0 + r) * D + rect * 32 + ob2);
            op[0] = make_ulonglong2(acc[r][0], acc[r][1]);
            op[1] = make_ulonglong2(acc[r][2], acc[r][3]);
        }
    }
}

extern "C" void kernel_launch(void* const* d_in, const int* in_sizes, int n_in,
                              void* d_out, int out_size) {
    const float* x  = (const float*)d_in[0];   // [4,4096,4096] f32
    const float* iB = (const float*)d_in[1];   // [2,64,64,64]  f32
    const float* fB = (const float*)d_in[2];   // [128,32,32]   f32
    float* out = (float*)d_out;                // [4,4096,4096] f32

    prep_kernel<<<64, 128>>>(iB);

    const int smem = ROWS * D * sizeof(float); // 131072 bytes
    cudaFuncSetAttribute(bh_fused_kernel,
                         cudaFuncAttributeMaxDynamicSharedMemorySize, smem);
    const int nrows = 4 * 4096;
    bh_fused_kernel<<<nrows / ROWS, THREADS, smem>>>(x, fB, out);
}